// round 11
// baseline (speedup 1.0000x reference)
#include <cuda_runtime.h>

#define EPSF 1e-6f
#define S 32
#define C 3
#define TILE (S * S)   // 1024

// Precomputed Thomas factorizations, float4-packed (2 i-steps per entry):
//   g_cf4[(j*C+c)*512 + m*32 + r] = (invd_{2m}, w_{2m}, invd_{2m+1}, w_{2m+1})
// for row r. j=0..5 x-dir, 6..10 y-dir. c_star = -w, so the backward sweep
// is x_i = d_i + w_i * x_{i+1}.
__device__ __align__(128) float4 g_cf4[11 * C * (TILE / 2)];

// solve order over the 15 substeps, as j-indices into the table
__constant__ int c_jseq[15] = {0, 6, 1, 1, 7, 2, 2, 8, 3, 3, 9, 4, 4, 10, 5};

// ---------------------------------------------------------------------------
// packed f32x2 helpers (PTX-only; ptxas never auto-fuses)
// ---------------------------------------------------------------------------
__device__ __forceinline__ float2 fma2(float2 a, float2 b, float2 c) {
    unsigned long long au = *reinterpret_cast<unsigned long long*>(&a);
    unsigned long long bu = *reinterpret_cast<unsigned long long*>(&b);
    unsigned long long cu = *reinterpret_cast<unsigned long long*>(&c);
    unsigned long long du;
    asm("fma.rn.f32x2 %0, %1, %2, %3;" : "=l"(du) : "l"(au), "l"(bu), "l"(cu));
    return *reinterpret_cast<float2*>(&du);
}
__device__ __forceinline__ float2 mul2(float2 a, float2 b) {
    unsigned long long au = *reinterpret_cast<unsigned long long*>(&a);
    unsigned long long bu = *reinterpret_cast<unsigned long long*>(&b);
    unsigned long long du;
    asm("mul.rn.f32x2 %0, %1, %2;" : "=l"(du) : "l"(au), "l"(bu));
    return *reinterpret_cast<float2*>(&du);
}

// ---------------------------------------------------------------------------
// Precompute kernel: one thread per (timeIdx, c, row). 11*3*32 = 1056 threads.
// ---------------------------------------------------------------------------
__global__ void precompute_kernel(const float* __restrict__ ab,
                                  const float* __restrict__ bb,
                                  const float* __restrict__ atc,
                                  const float* __restrict__ btc) {
    int tid = blockIdx.x * blockDim.x + threadIdx.x;
    if (tid >= 11 * C * S) return;
    int j   = tid / (C * S);
    int rem = tid % (C * S);
    int c   = rem / S;
    int r   = rem % S;

    float t, fac;
    const float* bp;
    const float* tp;
    int stride;
    if (j < 6) {                       // x-direction, t = j*DT, dt = DT/2
        t   = (float)(j * 0.1);
        fac = 0.05f;
        bp  = ab + (c * S + r) * S;
        tp  = atc + (c * S + r) * S;
        stride = 1;
    } else {                           // y-direction, t = DT/2 + jy*DT, dt = DT
        int jy = j - 6;
        t   = (float)(0.05 + jy * 0.1);
        fac = 0.1f;
        bp  = bb + c * TILE + r;
        tp  = btc + c * TILE + r;
        stride = S;
    }
    float4* out4 = g_cf4 + (j * C + c) * (TILE / 2);

    float coef[S];
#pragma unroll
    for (int i = 0; i < S; ++i)
        coef[i] = fmaxf(bp[i * stride] + t * tp[i * stride], EPSF);

    float cs[S];
    cs[0] = (coef[0] + coef[0] + coef[1]) / 3.0f * fac;
#pragma unroll
    for (int i = 1; i < S - 1; ++i)
        cs[i] = (coef[i - 1] + coef[i] + coef[i + 1]) / 3.0f * fac;
    cs[S - 1] = (coef[S - 2] + coef[S - 1] + coef[S - 1]) / 3.0f * fac;

    float invd[S], wv[S];
    float wprev = 0.0f;
#pragma unroll
    for (int i = 0; i < S; ++i) {
        float b = 1.0f + 2.0f * cs[i];
        if (i == 0)     b = 1.0f + cs[0];
        if (i == S - 1) b = 1.0f + cs[S - 1];
        float denom = b - cs[i] * wprev + EPSF;
        invd[i] = 1.0f / denom;
        wv[i]   = cs[i] * invd[i];
        wprev = wv[i];
    }
#pragma unroll
    for (int m = 0; m < S / 2; ++m)
        out4[m * S + r] = make_float4(invd[2 * m], wv[2 * m],
                                      invd[2 * m + 1], wv[2 * m + 1]);
}

// ---------------------------------------------------------------------------
// Main fused ADI kernel: ONE warp per CTA, K=4 tiles as TWO f32x2 pairs.
// Coefficients via direct LDG.128 (float4 = 2 i-steps), 2-deep pipeline.
// warr[] in registers (proven). regs capped at 186 -> 11 CTAs/SM, single wave.
// ---------------------------------------------------------------------------
__global__ __launch_bounds__(32, 11)
void adi_kernel(const float* __restrict__ uin, float* __restrict__ uout) {
    __shared__ float2 sm[S * 33];   // 8.4KB transpose slab

    const int lane = threadIdx.x;
    const int cid  = blockIdx.x % C;
    const int bg   = blockIdx.x / C;                    // 0..511 batch-quad
    const int base0 = (4 * bg) * C * TILE + cid * TILE; // tile k at +k*C*TILE

    float2 v0[S], v1[S];   // pair0 = tiles (0,1), pair1 = tiles (2,3)
    float  warr[S];

    // ---- load: direct coalesced LDG, column layout v[i] = u[row i][col lane]
#pragma unroll
    for (int i = 0; i < S; ++i) {
        v0[i].x = uin[base0 + 0 * C * TILE + i * S + lane];
        v0[i].y = uin[base0 + 1 * C * TILE + i * S + lane];
        v1[i].x = uin[base0 + 2 * C * TILE + i * S + lane];
        v1[i].y = uin[base0 + 3 * C * TILE + i * S + lane];
    }

    // ---- 32x32 transpose of both pairs through one padded slab ----
    auto transpose = [&]() {
        __syncwarp();
#pragma unroll
        for (int i = 0; i < S; ++i) sm[lane * 33 + i] = v0[i];
        __syncwarp();
#pragma unroll
        for (int i = 0; i < S; ++i) v0[i] = sm[i * 33 + lane];
        __syncwarp();
#pragma unroll
        for (int i = 0; i < S; ++i) sm[lane * 33 + i] = v1[i];
        __syncwarp();
#pragma unroll
        for (int i = 0; i < S; ++i) v1[i] = sm[i * 33 + lane];
        __syncwarp();
    };

    // ---- Thomas solve: LDG.128 coeff stream, two independent f32x2 chains --
    auto solve = [&](int j) {
        const float4* __restrict__ cf4 = g_cf4 + (j * C + cid) * (TILE / 2);
        float4 cb[2];
        cb[0] = __ldg(&cf4[lane]);            // m=0
        cb[1] = __ldg(&cf4[S + lane]);        // m=1
        float2 dp0 = make_float2(0.0f, 0.0f);
        float2 dp1 = make_float2(0.0f, 0.0f);
#pragma unroll
        for (int m = 0; m < S / 2; ++m) {
            float4 iw = cb[m & 1];
            if (m < S / 2 - 2)
                cb[m & 1] = __ldg(&cf4[(m + 2) * S + lane]);
            // i = 2m
            {
                const int i = 2 * m;
                warr[i] = iw.y;
                float2 t0 = mul2(v0[i], make_float2(iw.x, iw.x));
                float2 t1 = mul2(v1[i], make_float2(iw.x, iw.x));
                t0 = fma2(make_float2(iw.y, iw.y), dp0, t0);
                t1 = fma2(make_float2(iw.y, iw.y), dp1, t1);
                v0[i] = t0; dp0 = t0;
                v1[i] = t1; dp1 = t1;
            }
            // i = 2m+1
            {
                const int i = 2 * m + 1;
                warr[i] = iw.w;
                float2 t0 = mul2(v0[i], make_float2(iw.z, iw.z));
                float2 t1 = mul2(v1[i], make_float2(iw.z, iw.z));
                t0 = fma2(make_float2(iw.w, iw.w), dp0, t0);
                t1 = fma2(make_float2(iw.w, iw.w), dp1, t1);
                v0[i] = t0; dp0 = t0;
                v1[i] = t1; dp1 = t1;
            }
        }
        // backward sweep: w from registers, two interleaved 4-cyc chains
#pragma unroll
        for (int i = S - 2; i >= 0; --i) {
            float2 w2 = make_float2(warr[i], warr[i]);
            v0[i] = fma2(w2, v0[i + 1], v0[i]);
            v1[i] = fma2(w2, v1[i + 1], v1[i]);
        }
    };

    // loaded column layout -> row layout for first X solve
    transpose();

    // 15 substeps: X0 Y0 X1 X1 Y1 X2 X2 Y2 X3 X3 Y3 X4 X4 Y4 X5
#pragma unroll 1
    for (int s = 0; s < 15; ++s) {
        const int j = c_jseq[s];
        solve(j);
        if (s < 14 && ((j < 6) != (c_jseq[s + 1] < 6)))
            transpose();
    }

    // row layout -> column layout, then direct coalesced STG
    transpose();
#pragma unroll
    for (int i = 0; i < S; ++i) {
        uout[base0 + 0 * C * TILE + i * S + lane] = v0[i].x;
        uout[base0 + 1 * C * TILE + i * S + lane] = v0[i].y;
        uout[base0 + 2 * C * TILE + i * S + lane] = v1[i].x;
        uout[base0 + 3 * C * TILE + i * S + lane] = v1[i].y;
    }
}

// ---------------------------------------------------------------------------
extern "C" void kernel_launch(void* const* d_in, const int* in_sizes, int n_in,
                              void* d_out, int out_size) {
    const float* u   = (const float*)d_in[0];
    const float* ab  = (const float*)d_in[1];
    const float* bb  = (const float*)d_in[2];
    const float* atc = (const float*)d_in[3];
    const float* btc = (const float*)d_in[4];
    float* out = (float*)d_out;

    const int B = in_sizes[0] / (C * TILE);   // 2048

    precompute_kernel<<<(11 * C * S + 127) / 128, 128>>>(ab, bb, atc, btc);

    const int nquads = B / 4;                 // 512
    adi_kernel<<<nquads * C, 32>>>(u, out);   // 1536 one-warp CTAs
}

// round 12
// speedup vs baseline: 1.2911x; 1.2911x over previous
#include <cuda_runtime.h>

#define EPSF 1e-6f
#define S 32
#define C 3
#define TILE (S * S)   // 1024

// Precomputed Thomas factorizations, 11 time-indices (j=0..5 x-dir, 6..10 y-dir):
//   g_cf2[(j*C+c)*TILE + i*S + r] = (invd, w)
// c_star = -w, so backward sweep is x_i = d_i + w_i * x_{i+1}.
__device__ __align__(128) float2 g_cf2[11 * C * TILE];

// solve order over the 15 substeps, as j-indices into the table
__constant__ int c_jseq[15] = {0, 6, 1, 1, 7, 2, 2, 8, 3, 3, 9, 4, 4, 10, 5};

// ---------------------------------------------------------------------------
// packed f32x2 + cp.async helpers (PTX-only)
// ---------------------------------------------------------------------------
__device__ __forceinline__ float2 fma2(float2 a, float2 b, float2 c) {
    unsigned long long au = *reinterpret_cast<unsigned long long*>(&a);
    unsigned long long bu = *reinterpret_cast<unsigned long long*>(&b);
    unsigned long long cu = *reinterpret_cast<unsigned long long*>(&c);
    unsigned long long du;
    asm("fma.rn.f32x2 %0, %1, %2, %3;" : "=l"(du) : "l"(au), "l"(bu), "l"(cu));
    return *reinterpret_cast<float2*>(&du);
}
__device__ __forceinline__ float2 mul2(float2 a, float2 b) {
    unsigned long long au = *reinterpret_cast<unsigned long long*>(&a);
    unsigned long long bu = *reinterpret_cast<unsigned long long*>(&b);
    unsigned long long du;
    asm("mul.rn.f32x2 %0, %1, %2;" : "=l"(du) : "l"(au), "l"(bu));
    return *reinterpret_cast<float2*>(&du);
}
__device__ __forceinline__ void cp16(unsigned sdst, const void* gsrc) {
    asm volatile("cp.async.cg.shared.global [%0], [%1], 16;"
                 :: "r"(sdst), "l"(gsrc));
}
__device__ __forceinline__ void cp_commit() {
    asm volatile("cp.async.commit_group;" ::: "memory");
}
template <int N>
__device__ __forceinline__ void cp_wait() {
    asm volatile("cp.async.wait_group %0;" :: "n"(N) : "memory");
}

// ---------------------------------------------------------------------------
// Precompute kernel: one thread per (timeIdx, c, row). 11*3*32 = 1056 threads.
// ---------------------------------------------------------------------------
__global__ void precompute_kernel(const float* __restrict__ ab,
                                  const float* __restrict__ bb,
                                  const float* __restrict__ atc,
                                  const float* __restrict__ btc) {
    int tid = blockIdx.x * blockDim.x + threadIdx.x;
    if (tid >= 11 * C * S) return;
    int j   = tid / (C * S);
    int rem = tid % (C * S);
    int c   = rem / S;
    int r   = rem % S;

    float t, fac;
    const float* bp;
    const float* tp;
    int stride;
    if (j < 6) {                       // x-direction, t = j*DT, dt = DT/2
        t   = (float)(j * 0.1);
        fac = 0.05f;
        bp  = ab + (c * S + r) * S;
        tp  = atc + (c * S + r) * S;
        stride = 1;
    } else {                           // y-direction, t = DT/2 + jy*DT, dt = DT
        int jy = j - 6;
        t   = (float)(0.05 + jy * 0.1);
        fac = 0.1f;
        bp  = bb + c * TILE + r;
        tp  = btc + c * TILE + r;
        stride = S;
    }
    float2* out2 = g_cf2 + (j * C + c) * TILE;

    float coef[S];
#pragma unroll
    for (int i = 0; i < S; ++i)
        coef[i] = fmaxf(bp[i * stride] + t * tp[i * stride], EPSF);

    float cs[S];
    cs[0] = (coef[0] + coef[0] + coef[1]) / 3.0f * fac;
#pragma unroll
    for (int i = 1; i < S - 1; ++i)
        cs[i] = (coef[i - 1] + coef[i] + coef[i + 1]) / 3.0f * fac;
    cs[S - 1] = (coef[S - 2] + coef[S - 1] + coef[S - 1]) / 3.0f * fac;

    float wprev = 0.0f;
#pragma unroll
    for (int i = 0; i < S; ++i) {
        float b = 1.0f + 2.0f * cs[i];
        if (i == 0)     b = 1.0f + cs[0];
        if (i == S - 1) b = 1.0f + cs[S - 1];
        float denom = b - cs[i] * wprev + EPSF;
        float invd  = 1.0f / denom;
        float w     = cs[i] * invd;
        out2[i * S + r] = make_float2(invd, w);
        wprev = w;
    }
}

// ---------------------------------------------------------------------------
// Main fused ADI kernel: 4 warps/CTA (shared channel c), each warp K=4 tiles
// as TWO f32x2 pairs. The CTA shares ONE cp.async double-buffered smem
// coefficient table (fetched once per solve, one-solve lookahead); the solve
// reads it via the R8 cb[2][4] LDS ping-pong (29-cyc latency, fully covered).
// warr[] stays in registers. launch_bounds(128,2) -> cap 256, no reg squeeze.
// ---------------------------------------------------------------------------
__global__ __launch_bounds__(128, 2)
void adi_kernel(const float* __restrict__ uin, float* __restrict__ uout) {
    __shared__ __align__(16) float2 cbuf[2][TILE];   // 2 x 8KB shared coeff
    __shared__ float2 slabs[4][TILE];                // 4 x 8KB XOR-swizzled

    const int lane = threadIdx.x & 31;
    const int wip  = threadIdx.x >> 5;
    float2* slab = slabs[wip];

    const int cid = blockIdx.x % C;                     // same c for whole CTA
    const int grp = blockIdx.x / C;                     // 0..127
    const int bg  = grp * 4 + wip;                      // 0..511 batch-quad
    const int base0 = (4 * bg) * C * TILE + cid * TILE; // tile k at +k*C*TILE

    // cooperative cp.async fetch of one 8KB table (64B per thread)
    auto fetch = [&](int b, int j) {
        unsigned sdst = (unsigned)__cvta_generic_to_shared(&cbuf[b][0])
                      + threadIdx.x * 16;
        const char* gsrc = (const char*)(g_cf2 + (j * C + cid) * TILE)
                         + threadIdx.x * 16;
#pragma unroll
        for (int it = 0; it < 4; ++it)
            cp16(sdst + it * 2048, gsrc + it * 2048);
        cp_commit();
    };

    // prologue: start fetching the first table immediately
    fetch(0, c_jseq[0]);

    float2 v0[S], v1[S];   // pair0 = tiles (0,1), pair1 = tiles (2,3)
    float  warr[S];

    // ---- load: direct coalesced LDG, column layout v[i] = u[row i][col lane]
#pragma unroll
    for (int i = 0; i < S; ++i) {
        v0[i].x = uin[base0 + 0 * C * TILE + i * S + lane];
        v0[i].y = uin[base0 + 1 * C * TILE + i * S + lane];
        v1[i].x = uin[base0 + 2 * C * TILE + i * S + lane];
        v1[i].y = uin[base0 + 3 * C * TILE + i * S + lane];
    }

    // ---- 32x32 transpose of both pairs via XOR-swizzled private slab ----
    // write slab[lane*32 + (i^lane)] = v[i]; read v[i] = slab[i*32 + (lane^i)]
    // -> conflict-free both phases, exactly 8KB (no padding).
    auto transpose = [&]() {
        __syncwarp();
#pragma unroll
        for (int i = 0; i < S; ++i) slab[lane * S + (i ^ lane)] = v0[i];
        __syncwarp();
#pragma unroll
        for (int i = 0; i < S; ++i) v0[i] = slab[i * S + (lane ^ i)];
        __syncwarp();
#pragma unroll
        for (int i = 0; i < S; ++i) slab[lane * S + (i ^ lane)] = v1[i];
        __syncwarp();
#pragma unroll
        for (int i = 0; i < S; ++i) v1[i] = slab[i * S + (lane ^ i)];
        __syncwarp();
    };

    // ---- Thomas solve: smem coeff stream (cb ping-pong), two f32x2 chains --
    auto solve = [&](int buf) {
        const float2* __restrict__ sc = cbuf[buf];
        float2 cb[2][4];
#pragma unroll
        for (int m = 0; m < 4; ++m)
            cb[0][m] = sc[m * S + lane];
        float2 dp0 = make_float2(0.0f, 0.0f);
        float2 dp1 = make_float2(0.0f, 0.0f);
#pragma unroll
        for (int blk = 0; blk < 8; ++blk) {
            if (blk < 7) {
#pragma unroll
                for (int m = 0; m < 4; ++m)
                    cb[(blk + 1) & 1][m] = sc[((blk + 1) * 4 + m) * S + lane];
            }
#pragma unroll
            for (int m = 0; m < 4; ++m) {
                const int i = blk * 4 + m;
                float2 iw = cb[blk & 1][m];
                warr[i] = iw.y;
                float2 inv2 = make_float2(iw.x, iw.x);
                float2 w2   = make_float2(iw.y, iw.y);
                float2 t0 = mul2(v0[i], inv2);
                float2 t1 = mul2(v1[i], inv2);
                t0 = fma2(w2, dp0, t0);
                t1 = fma2(w2, dp1, t1);
                v0[i] = t0; dp0 = t0;
                v1[i] = t1; dp1 = t1;
            }
        }
        // backward sweep: w from registers, two interleaved 4-cyc chains
#pragma unroll
        for (int i = S - 2; i >= 0; --i) {
            float2 w2 = make_float2(warr[i], warr[i]);
            v0[i] = fma2(w2, v0[i + 1], v0[i]);
            v1[i] = fma2(w2, v1[i + 1], v1[i]);
        }
    };

    // loaded column layout -> row layout for first X solve
    transpose();

    // 15 substeps: X0 Y0 X1 X1 Y1 X2 X2 Y2 X3 X3 Y3 X4 X4 Y4 X5
#pragma unroll 1
    for (int s = 0; s < 15; ++s) {
        if (s < 14) {
            __syncthreads();               // all warps done reading buf[(s+1)&1]
            fetch((s + 1) & 1, c_jseq[s + 1]);
            cp_wait<1>();                  // fetch(s) complete
        } else {
            cp_wait<0>();
        }
        __syncthreads();                   // fetch(s) visible CTA-wide
        solve(s & 1);
        if (s < 14 && ((c_jseq[s] < 6) != (c_jseq[s + 1] < 6)))
            transpose();
    }

    // row layout -> column layout, then direct coalesced STG
    transpose();
#pragma unroll
    for (int i = 0; i < S; ++i) {
        uout[base0 + 0 * C * TILE + i * S + lane] = v0[i].x;
        uout[base0 + 1 * C * TILE + i * S + lane] = v0[i].y;
        uout[base0 + 2 * C * TILE + i * S + lane] = v1[i].x;
        uout[base0 + 3 * C * TILE + i * S + lane] = v1[i].y;
    }
}

// ---------------------------------------------------------------------------
extern "C" void kernel_launch(void* const* d_in, const int* in_sizes, int n_in,
                              void* d_out, int out_size) {
    const float* u   = (const float*)d_in[0];
    const float* ab  = (const float*)d_in[1];
    const float* bb  = (const float*)d_in[2];
    const float* atc = (const float*)d_in[3];
    const float* btc = (const float*)d_in[4];
    float* out = (float*)d_out;

    const int B = in_sizes[0] / (C * TILE);   // 2048

    precompute_kernel<<<(11 * C * S + 127) / 128, 128>>>(ab, bb, atc, btc);

    const int nquads = B / 4;                 // 512
    const int nctas  = (nquads * C) / 4;      // 384 four-warp CTAs
    adi_kernel<<<nctas, 128>>>(u, out);
}

// round 13
// speedup vs baseline: 1.8505x; 1.4333x over previous
#include <cuda_runtime.h>

#define EPSF 1e-6f
#define S 32
#define C 3
#define TILE (S * S)   // 1024
#define PAD 33

// Precomputed Thomas factorizations, 11 time-indices (j=0..5 x-dir, 6..10 y-dir):
//   g_cf2[(j*C+c)*TILE + i*S + r] = (invd, w)
// c_star = -w, so backward sweep is x_i = d_i + w_i * x_{i+1}.
__device__ __align__(128) float2 g_cf2[11 * C * TILE];

// ---------------------------------------------------------------------------
// packed f32x2 helpers (PTX-only; ptxas never auto-fuses)
// ---------------------------------------------------------------------------
__device__ __forceinline__ float2 fma2(float2 a, float2 b, float2 c) {
    unsigned long long au = *reinterpret_cast<unsigned long long*>(&a);
    unsigned long long bu = *reinterpret_cast<unsigned long long*>(&b);
    unsigned long long cu = *reinterpret_cast<unsigned long long*>(&c);
    unsigned long long du;
    asm("fma.rn.f32x2 %0, %1, %2, %3;" : "=l"(du) : "l"(au), "l"(bu), "l"(cu));
    return *reinterpret_cast<float2*>(&du);
}
__device__ __forceinline__ float2 mul2(float2 a, float2 b) {
    unsigned long long au = *reinterpret_cast<unsigned long long*>(&a);
    unsigned long long bu = *reinterpret_cast<unsigned long long*>(&b);
    unsigned long long du;
    asm("mul.rn.f32x2 %0, %1, %2;" : "=l"(du) : "l"(au), "l"(bu));
    return *reinterpret_cast<float2*>(&du);
}

// ---------------------------------------------------------------------------
// Precompute kernel: one thread per (timeIdx, c, row). 11*3*32 = 1056 threads.
// ---------------------------------------------------------------------------
__global__ void precompute_kernel(const float* __restrict__ ab,
                                  const float* __restrict__ bb,
                                  const float* __restrict__ atc,
                                  const float* __restrict__ btc) {
    int tid = blockIdx.x * blockDim.x + threadIdx.x;
    if (tid >= 11 * C * S) return;
    int j   = tid / (C * S);
    int rem = tid % (C * S);
    int c   = rem / S;
    int r   = rem % S;

    float t, fac;
    const float* bp;
    const float* tp;
    int stride;
    if (j < 6) {                       // x-direction, t = j*DT, dt = DT/2
        t   = (float)(j * 0.1);
        fac = 0.05f;
        bp  = ab + (c * S + r) * S;
        tp  = atc + (c * S + r) * S;
        stride = 1;
    } else {                           // y-direction, t = DT/2 + jy*DT, dt = DT
        int jy = j - 6;
        t   = (float)(0.05 + jy * 0.1);
        fac = 0.1f;
        bp  = bb + c * TILE + r;
        tp  = btc + c * TILE + r;
        stride = S;
    }
    float2* out2 = g_cf2 + (j * C + c) * TILE;

    float coef[S];
#pragma unroll
    for (int i = 0; i < S; ++i)
        coef[i] = fmaxf(bp[i * stride] + t * tp[i * stride], EPSF);

    float cs[S];
    cs[0] = (coef[0] + coef[0] + coef[1]) / 3.0f * fac;
#pragma unroll
    for (int i = 1; i < S - 1; ++i)
        cs[i] = (coef[i - 1] + coef[i] + coef[i + 1]) / 3.0f * fac;
    cs[S - 1] = (coef[S - 2] + coef[S - 1] + coef[S - 1]) / 3.0f * fac;

    float wprev = 0.0f;
#pragma unroll
    for (int i = 0; i < S; ++i) {
        float b = 1.0f + 2.0f * cs[i];
        if (i == 0)     b = 1.0f + cs[0];
        if (i == S - 1) b = 1.0f + cs[S - 1];
        float denom = b - cs[i] * wprev + EPSF;
        float invd  = 1.0f / denom;
        float w     = cs[i] * invd;
        out2[i * S + r] = make_float2(invd, w);
        wprev = w;
    }
}

// ---------------------------------------------------------------------------
// Fused-transpose Thomas solve.
// Canonical slab frame: slab[h*PAD + w] = value at (h, w).
// DIR=0 (X solve): element (h=lane, w=i)  -> slab index lane*PAD + i
// DIR=1 (Y solve): element (h=i, w=lane)  -> slab index i*PAD + lane
// INS:  forward sweep reads input from slab (boundary) instead of v regs.
// OUTS: backward sweep stores results to slab (boundary) as it computes.
// ---------------------------------------------------------------------------
template <int DIR, bool INS, bool OUTS>
__device__ __forceinline__ void solve_t(const float2* __restrict__ cf2, int lane,
                                        float2* __restrict__ v0,
                                        float2* __restrict__ v1,
                                        float*  __restrict__ warr,
                                        float2* __restrict__ sA,
                                        float2* __restrict__ sB) {
#define IDX(i) (DIR == 0 ? (lane * PAD + (i)) : ((i) * PAD + lane))
    // forward sweep: coeff LDG ping-pong (R8 core), two independent chains
    float2 cb[2][4];
#pragma unroll
    for (int m = 0; m < 4; ++m)
        cb[0][m] = __ldg(&cf2[m * S + lane]);
    float2 dp0 = make_float2(0.0f, 0.0f);
    float2 dp1 = make_float2(0.0f, 0.0f);
#pragma unroll
    for (int blk = 0; blk < 8; ++blk) {
        if (blk < 7) {
#pragma unroll
            for (int m = 0; m < 4; ++m)
                cb[(blk + 1) & 1][m] = __ldg(&cf2[((blk + 1) * 4 + m) * S + lane]);
        }
#pragma unroll
        for (int m = 0; m < 4; ++m) {
            const int i = blk * 4 + m;
            float2 iw = cb[blk & 1][m];
            warr[i] = iw.y;
            float2 x0 = INS ? sA[IDX(i)] : v0[i];
            float2 x1 = INS ? sB[IDX(i)] : v1[i];
            float2 inv2 = make_float2(iw.x, iw.x);
            float2 w2   = make_float2(iw.y, iw.y);
            float2 t0 = mul2(x0, inv2);
            float2 t1 = mul2(x1, inv2);
            t0 = fma2(w2, dp0, t0);
            t1 = fma2(w2, dp1, t1);
            v0[i] = t0; dp0 = t0;
            v1[i] = t1; dp1 = t1;
        }
    }
    __syncwarp();
    // backward sweep: w from registers; stores fused into the loop
    if (OUTS) {
        sA[IDX(31)] = v0[31];
        sB[IDX(31)] = v1[31];
    }
#pragma unroll
    for (int i = S - 2; i >= 0; --i) {
        float2 w2 = make_float2(warr[i], warr[i]);
        float2 r0 = fma2(w2, v0[i + 1], v0[i]);
        float2 r1 = fma2(w2, v1[i + 1], v1[i]);
        v0[i] = r0;
        v1[i] = r1;
        if (OUTS) {
            sA[IDX(i)] = r0;
            sB[IDX(i)] = r1;
        }
    }
    __syncwarp();
#undef IDX
}

// ---------------------------------------------------------------------------
// Main fused ADI kernel: ONE warp per CTA, K=4 tiles as TWO f32x2 pairs.
// Transposes are fused into solve I/O via the canonical slabs: no standalone
// transpose phases. Same-direction X-X transitions stay in registers.
// ---------------------------------------------------------------------------
__global__ __launch_bounds__(32, 8)
void adi_kernel(const float* __restrict__ uin, float* __restrict__ uout) {
    __shared__ float2 sA[S * PAD];   // pair0 canonical slab
    __shared__ float2 sB[S * PAD];   // pair1 canonical slab

    const int lane = threadIdx.x;
    const int cid  = blockIdx.x % C;
    const int bg   = blockIdx.x / C;                    // 0..511 batch-quad
    const int base0 = (4 * bg) * C * TILE + cid * TILE; // tile k at +k*C*TILE

    float2 v0[S], v1[S];
    float  warr[S];

    // ---- load: coalesced LDG -> canonical slabs (value(h=i, w=lane)) ----
#pragma unroll 8
    for (int i = 0; i < S; ++i) {
        sA[i * PAD + lane] = make_float2(uin[base0 + 0 * C * TILE + i * S + lane],
                                         uin[base0 + 1 * C * TILE + i * S + lane]);
        sB[i * PAD + lane] = make_float2(uin[base0 + 2 * C * TILE + i * S + lane],
                                         uin[base0 + 3 * C * TILE + i * S + lane]);
    }
    __syncwarp();

    const float2* tab = g_cf2 + cid * TILE;   // + j*C*TILE per time index
    const int CT = C * TILE;

    // X0: slab -> slab
    solve_t<0, true, true>(tab + 0 * CT, lane, v0, v1, warr, sA, sB);
    // [Y_it, X_{it+1}(regs-out? no: slab->regs), X_{it+1}(regs->slab)] x4
#pragma unroll 1
    for (int it = 0; it < 4; ++it) {
        solve_t<1, true, true >(tab + (6 + it) * CT, lane, v0, v1, warr, sA, sB);
        solve_t<0, true, false>(tab + (it + 1) * CT, lane, v0, v1, warr, sA, sB);
        solve_t<0, false, true>(tab + (it + 1) * CT, lane, v0, v1, warr, sA, sB);
    }
    // Y4: slab -> slab
    solve_t<1, true, true>(tab + 10 * CT, lane, v0, v1, warr, sA, sB);
    // X5: slab -> slab (canonical frame)
    solve_t<0, true, true>(tab + 5 * CT, lane, v0, v1, warr, sA, sB);

    // ---- store: canonical slabs -> coalesced STG ----
#pragma unroll 8
    for (int i = 0; i < S; ++i) {
        float2 a = sA[i * PAD + lane];
        float2 b = sB[i * PAD + lane];
        uout[base0 + 0 * C * TILE + i * S + lane] = a.x;
        uout[base0 + 1 * C * TILE + i * S + lane] = a.y;
        uout[base0 + 2 * C * TILE + i * S + lane] = b.x;
        uout[base0 + 3 * C * TILE + i * S + lane] = b.y;
    }
}

// ---------------------------------------------------------------------------
extern "C" void kernel_launch(void* const* d_in, const int* in_sizes, int n_in,
                              void* d_out, int out_size) {
    const float* u   = (const float*)d_in[0];
    const float* ab  = (const float*)d_in[1];
    const float* bb  = (const float*)d_in[2];
    const float* atc = (const float*)d_in[3];
    const float* btc = (const float*)d_in[4];
    float* out = (float*)d_out;

    const int B = in_sizes[0] / (C * TILE);   // 2048

    precompute_kernel<<<(11 * C * S + 127) / 128, 128>>>(ab, bb, atc, btc);

    const int nquads = B / 4;                 // 512
    adi_kernel<<<nquads * C, 32>>>(u, out);   // 1536 one-warp CTAs
}

// round 14
// speedup vs baseline: 1.8609x; 1.0056x over previous
#include <cuda_runtime.h>

#define EPSF 1e-6f
#define S 32
#define C 3
#define TILE (S * S)   // 1024
#define PAD 33

// Precomputed Thomas factorizations, 11 time-indices (j=0..5 x-dir, 6..10 y-dir):
//   g_cf2[(j*C+c)*TILE + i*S + r] = (invd, w)
// c_star = -w, so backward sweep is x_i = d_i + w_i * x_{i+1}.
__device__ __align__(128) float2 g_cf2[11 * C * TILE];

// ---------------------------------------------------------------------------
// packed f32x2 + streaming-io helpers (PTX-only)
// ---------------------------------------------------------------------------
__device__ __forceinline__ float2 fma2(float2 a, float2 b, float2 c) {
    unsigned long long au = *reinterpret_cast<unsigned long long*>(&a);
    unsigned long long bu = *reinterpret_cast<unsigned long long*>(&b);
    unsigned long long cu = *reinterpret_cast<unsigned long long*>(&c);
    unsigned long long du;
    asm("fma.rn.f32x2 %0, %1, %2, %3;" : "=l"(du) : "l"(au), "l"(bu), "l"(cu));
    return *reinterpret_cast<float2*>(&du);
}
__device__ __forceinline__ float2 mul2(float2 a, float2 b) {
    unsigned long long au = *reinterpret_cast<unsigned long long*>(&a);
    unsigned long long bu = *reinterpret_cast<unsigned long long*>(&b);
    unsigned long long du;
    asm("mul.rn.f32x2 %0, %1, %2;" : "=l"(du) : "l"(au), "l"(bu));
    return *reinterpret_cast<float2*>(&du);
}

// ---------------------------------------------------------------------------
// Precompute kernel: one thread per (timeIdx, c, row). 11*3*32 = 1056 threads.
// ---------------------------------------------------------------------------
__global__ void precompute_kernel(const float* __restrict__ ab,
                                  const float* __restrict__ bb,
                                  const float* __restrict__ atc,
                                  const float* __restrict__ btc) {
    int tid = blockIdx.x * blockDim.x + threadIdx.x;
    if (tid >= 11 * C * S) return;
    int j   = tid / (C * S);
    int rem = tid % (C * S);
    int c   = rem / S;
    int r   = rem % S;

    float t, fac;
    const float* bp;
    const float* tp;
    int stride;
    if (j < 6) {                       // x-direction, t = j*DT, dt = DT/2
        t   = (float)(j * 0.1);
        fac = 0.05f;
        bp  = ab + (c * S + r) * S;
        tp  = atc + (c * S + r) * S;
        stride = 1;
    } else {                           // y-direction, t = DT/2 + jy*DT, dt = DT
        int jy = j - 6;
        t   = (float)(0.05 + jy * 0.1);
        fac = 0.1f;
        bp  = bb + c * TILE + r;
        tp  = btc + c * TILE + r;
        stride = S;
    }
    float2* out2 = g_cf2 + (j * C + c) * TILE;

    float coef[S];
#pragma unroll
    for (int i = 0; i < S; ++i)
        coef[i] = fmaxf(bp[i * stride] + t * tp[i * stride], EPSF);

    float cs[S];
    cs[0] = (coef[0] + coef[0] + coef[1]) / 3.0f * fac;
#pragma unroll
    for (int i = 1; i < S - 1; ++i)
        cs[i] = (coef[i - 1] + coef[i] + coef[i + 1]) / 3.0f * fac;
    cs[S - 1] = (coef[S - 2] + coef[S - 1] + coef[S - 1]) / 3.0f * fac;

    float wprev = 0.0f;
#pragma unroll
    for (int i = 0; i < S; ++i) {
        float b = 1.0f + 2.0f * cs[i];
        if (i == 0)     b = 1.0f + cs[0];
        if (i == S - 1) b = 1.0f + cs[S - 1];
        float denom = b - cs[i] * wprev + EPSF;
        float invd  = 1.0f / denom;
        float w     = cs[i] * invd;
        out2[i * S + r] = make_float2(invd, w);
        wprev = w;
    }
}

// ---------------------------------------------------------------------------
// Fused-transpose Thomas solve (R13 core, unchanged).
// Canonical slab frame: slab[h*PAD + w] = value at (h, w).
// DIR=0 (X solve): element (h=lane, w=i)  -> slab index lane*PAD + i
// DIR=1 (Y solve): element (h=i, w=lane)  -> slab index i*PAD + lane
// ---------------------------------------------------------------------------
template <int DIR, bool INS, bool OUTS>
__device__ __forceinline__ void solve_t(const float2* __restrict__ cf2, int lane,
                                        float2* __restrict__ v0,
                                        float2* __restrict__ v1,
                                        float*  __restrict__ warr,
                                        float2* __restrict__ sA,
                                        float2* __restrict__ sB) {
#define IDX(i) (DIR == 0 ? (lane * PAD + (i)) : ((i) * PAD + lane))
    float2 cb[2][4];
#pragma unroll
    for (int m = 0; m < 4; ++m)
        cb[0][m] = __ldg(&cf2[m * S + lane]);
    float2 dp0 = make_float2(0.0f, 0.0f);
    float2 dp1 = make_float2(0.0f, 0.0f);
#pragma unroll
    for (int blk = 0; blk < 8; ++blk) {
        if (blk < 7) {
#pragma unroll
            for (int m = 0; m < 4; ++m)
                cb[(blk + 1) & 1][m] = __ldg(&cf2[((blk + 1) * 4 + m) * S + lane]);
        }
#pragma unroll
        for (int m = 0; m < 4; ++m) {
            const int i = blk * 4 + m;
            float2 iw = cb[blk & 1][m];
            warr[i] = iw.y;
            float2 x0 = INS ? sA[IDX(i)] : v0[i];
            float2 x1 = INS ? sB[IDX(i)] : v1[i];
            float2 inv2 = make_float2(iw.x, iw.x);
            float2 w2   = make_float2(iw.y, iw.y);
            float2 t0 = mul2(x0, inv2);
            float2 t1 = mul2(x1, inv2);
            t0 = fma2(w2, dp0, t0);
            t1 = fma2(w2, dp1, t1);
            v0[i] = t0; dp0 = t0;
            v1[i] = t1; dp1 = t1;
        }
    }
    __syncwarp();
    if (OUTS) {
        sA[IDX(31)] = v0[31];
        sB[IDX(31)] = v1[31];
    }
#pragma unroll
    for (int i = S - 2; i >= 0; --i) {
        float2 w2 = make_float2(warr[i], warr[i]);
        float2 r0 = fma2(w2, v0[i + 1], v0[i]);
        float2 r1 = fma2(w2, v1[i + 1], v1[i]);
        v0[i] = r0;
        v1[i] = r1;
        if (OUTS) {
            sA[IDX(i)] = r0;
            sB[IDX(i)] = r1;
        }
    }
    __syncwarp();
#undef IDX
}

// ---------------------------------------------------------------------------
// Main fused ADI kernel: ONE warp per CTA, K=4 tiles as TWO f32x2 pairs.
// NEW vs R13:
//  * c-major block order: all CTAs resident on an SM share one channel ->
//    88KB coefficient table fits the L1D carveout -> coeff LDGs become L1 hits
//    that the 4-row cb lookahead fully covers.
//  * u-tile io uses __ldcs/__stcs (streaming) so it doesn't evict the table.
// ---------------------------------------------------------------------------
__global__ __launch_bounds__(32, 8)
void adi_kernel(const float* __restrict__ uin, float* __restrict__ uout) {
    __shared__ float2 sA[S * PAD];   // pair0 canonical slab
    __shared__ float2 sB[S * PAD];   // pair1 canonical slab

    const int lane   = threadIdx.x;
    const int nquads = gridDim.x / C;                   // 512
    const int cid    = blockIdx.x / nquads;             // c-major grouping
    const int bg     = blockIdx.x % nquads;             // 0..511 batch-quad
    const int base0  = (4 * bg) * C * TILE + cid * TILE;

    float2 v0[S], v1[S];
    float  warr[S];

    // ---- load: coalesced streaming LDG -> canonical slabs ----
#pragma unroll 8
    for (int i = 0; i < S; ++i) {
        sA[i * PAD + lane] = make_float2(__ldcs(&uin[base0 + 0 * C * TILE + i * S + lane]),
                                         __ldcs(&uin[base0 + 1 * C * TILE + i * S + lane]));
        sB[i * PAD + lane] = make_float2(__ldcs(&uin[base0 + 2 * C * TILE + i * S + lane]),
                                         __ldcs(&uin[base0 + 3 * C * TILE + i * S + lane]));
    }
    __syncwarp();

    const float2* tab = g_cf2 + cid * TILE;   // + j*C*TILE per time index
    const int CT = C * TILE;

    // X0: slab -> slab
    solve_t<0, true, true>(tab + 0 * CT, lane, v0, v1, warr, sA, sB);
    // [Y_it (slab->slab), X_{it+1} (slab->regs), X_{it+1} (regs->slab)] x4
#pragma unroll 1
    for (int it = 0; it < 4; ++it) {
        solve_t<1, true, true >(tab + (6 + it) * CT, lane, v0, v1, warr, sA, sB);
        solve_t<0, true, false>(tab + (it + 1) * CT, lane, v0, v1, warr, sA, sB);
        solve_t<0, false, true>(tab + (it + 1) * CT, lane, v0, v1, warr, sA, sB);
    }
    // Y4: slab -> slab
    solve_t<1, true, true>(tab + 10 * CT, lane, v0, v1, warr, sA, sB);
    // X5: slab -> slab (canonical frame)
    solve_t<0, true, true>(tab + 5 * CT, lane, v0, v1, warr, sA, sB);

    // ---- store: canonical slabs -> coalesced streaming STG ----
#pragma unroll 8
    for (int i = 0; i < S; ++i) {
        float2 a = sA[i * PAD + lane];
        float2 b = sB[i * PAD + lane];
        __stcs(&uout[base0 + 0 * C * TILE + i * S + lane], a.x);
        __stcs(&uout[base0 + 1 * C * TILE + i * S + lane], a.y);
        __stcs(&uout[base0 + 2 * C * TILE + i * S + lane], b.x);
        __stcs(&uout[base0 + 3 * C * TILE + i * S + lane], b.y);
    }
}

// ---------------------------------------------------------------------------
extern "C" void kernel_launch(void* const* d_in, const int* in_sizes, int n_in,
                              void* d_out, int out_size) {
    const float* u   = (const float*)d_in[0];
    const float* ab  = (const float*)d_in[1];
    const float* bb  = (const float*)d_in[2];
    const float* atc = (const float*)d_in[3];
    const float* btc = (const float*)d_in[4];
    float* out = (float*)d_out;

    const int B = in_sizes[0] / (C * TILE);   // 2048

    precompute_kernel<<<(11 * C * S + 127) / 128, 128>>>(ab, bb, atc, btc);

    const int nquads = B / 4;                 // 512
    adi_kernel<<<nquads * C, 32>>>(u, out);   // 1536 one-warp CTAs, c-major
}